// round 3
// baseline (speedup 1.0000x reference)
#include <cuda_runtime.h>
#include <cuda_bf16.h>
#include <math.h>
#include <stdint.h>

// ---------------------------------------------------------------------------
// Problem constants
// ---------------------------------------------------------------------------
#define BATCH    2
#define SEQ      2048
#define DMODEL   2048
#define DKV      512
#define DQ       1536
#define NHEADS   16
#define HDIM     128
#define ROWS     (BATCH*SEQ)            // 4096
#define QKDIM    256                    // concat(head, rope(head))
#define SCALE    0.0625f                // 1/sqrt(256)

#define OUT_SZ   (BATCH*SEQ*DMODEL)     // 8388608
#define CKV_SZ   (BATCH*SEQ*DKV)        // 2097152

// ---------------------------------------------------------------------------
// Scratch (no cudaMalloc allowed -> __device__ globals)
// ---------------------------------------------------------------------------
__device__ float g_cQ [ROWS*DQ];                 // 4096x1536
__device__ float g_kC [ROWS*DMODEL];             // 4096x2048
__device__ float g_vC [ROWS*DMODEL];             // 4096x2048
__device__ float g_qC [ROWS*DMODEL];             // 4096x2048
__device__ float g_q  [BATCH*NHEADS*SEQ*QKDIM];  // 16M
__device__ float g_k  [BATCH*NHEADS*SEQ*QKDIM];  // 16M
__device__ float g_ctx[ROWS*DMODEL];             // 4096x2048

// ---------------------------------------------------------------------------
// tf32 helpers
// ---------------------------------------------------------------------------
__device__ __forceinline__ uint32_t f2tf32(float x) {
    uint32_t r;
    asm("cvt.rna.tf32.f32 %0, %1;" : "=r"(r) : "f"(x));
    return r;
}

__device__ __forceinline__ void mma_tf32(float c[4],
                                         const uint32_t a[4],
                                         const uint32_t b[2]) {
    asm volatile(
        "mma.sync.aligned.m16n8k8.row.col.f32.tf32.tf32.f32 "
        "{%0,%1,%2,%3}, {%4,%5,%6,%7}, {%8,%9}, {%0,%1,%2,%3};\n"
        : "+f"(c[0]), "+f"(c[1]), "+f"(c[2]), "+f"(c[3])
        : "r"(a[0]), "r"(a[1]), "r"(a[2]), "r"(a[3]),
          "r"(b[0]), "r"(b[1]));
}

// ---------------------------------------------------------------------------
// TF32 tensor-core GEMM: C[M,N] = A[M,K] @ B[K,N] + bias[N]  (row-major fp32)
// 128x128 block, BK=32, 256 threads (8 warps, 2x4), warp tile 64x32.
// Register-prefetch double buffering.
// ---------------------------------------------------------------------------
#define GLDA 136   // smem leading dim (136 % 32 == 8 -> conflict-free frags)

__global__ __launch_bounds__(256) void tf32_gemm_bias(
    int M, int N, int K,
    const float* __restrict__ A, const float* __restrict__ B,
    const float* __restrict__ bias, float* __restrict__ C)
{
    __shared__ uint32_t As[32][GLDA];   // [k][m]  (transposed)
    __shared__ uint32_t Bs[32][GLDA];   // [k][n]

    const int tid  = threadIdx.x;
    const int bx   = blockIdx.x, by = blockIdx.y;
    const int warp = tid >> 5, lane = tid & 31;
    const int wm   = (warp >> 2) * 64;   // warp M offset
    const int wn   = (warp & 3) * 32;    // warp N offset
    const int g    = lane >> 2;          // groupID 0..7
    const int tg   = lane & 3;           // threadID_in_group 0..3

    const float* Ab = A + (size_t)(by * 128) * K;
    const float* Bb = B + bx * 128;

    float acc[4][4][4];
#pragma unroll
    for (int mt = 0; mt < 4; mt++)
#pragma unroll
        for (int nt = 0; nt < 4; nt++)
#pragma unroll
            for (int i = 0; i < 4; i++) acc[mt][nt][i] = 0.f;

    float4 pa[4], pb[4];

    // ---- initial tile load (k0 = 0) ----
#pragma unroll
    for (int i = 0; i < 4; i++) {
        int f4 = tid + 256 * i;
        int am = f4 >> 3, ak = (f4 & 7) * 4;
        pa[i] = *(const float4*)(Ab + (size_t)am * K + ak);
        int bk = f4 >> 5, bn = (f4 & 31) * 4;
        pb[i] = *(const float4*)(Bb + (size_t)bk * N + bn);
    }
#pragma unroll
    for (int i = 0; i < 4; i++) {
        int f4 = tid + 256 * i;
        int am = f4 >> 3, ak = (f4 & 7) * 4;
        As[ak + 0][am] = f2tf32(pa[i].x);
        As[ak + 1][am] = f2tf32(pa[i].y);
        As[ak + 2][am] = f2tf32(pa[i].z);
        As[ak + 3][am] = f2tf32(pa[i].w);
        int bk = f4 >> 5, bn = (f4 & 31) * 4;
        Bs[bk][bn + 0] = f2tf32(pb[i].x);
        Bs[bk][bn + 1] = f2tf32(pb[i].y);
        Bs[bk][bn + 2] = f2tf32(pb[i].z);
        Bs[bk][bn + 3] = f2tf32(pb[i].w);
    }
    __syncthreads();

    for (int k0 = 0;;) {
        const int knext = k0 + 32;
        const bool more = knext < K;

        // prefetch next tile into registers
        if (more) {
#pragma unroll
            for (int i = 0; i < 4; i++) {
                int f4 = tid + 256 * i;
                int am = f4 >> 3, ak = (f4 & 7) * 4;
                pa[i] = *(const float4*)(Ab + (size_t)am * K + knext + ak);
                int bk = f4 >> 5, bn = (f4 & 31) * 4;
                pb[i] = *(const float4*)(Bb + (size_t)(knext + bk) * N + bn);
            }
        }

        // compute current tile
#pragma unroll
        for (int ks = 0; ks < 32; ks += 8) {
            uint32_t af[4][4], bf[4][2];
#pragma unroll
            for (int mt = 0; mt < 4; mt++) {
                int m0 = wm + mt * 16;
                af[mt][0] = As[ks + tg][m0 + g];
                af[mt][1] = As[ks + tg][m0 + g + 8];
                af[mt][2] = As[ks + tg + 4][m0 + g];
                af[mt][3] = As[ks + tg + 4][m0 + g + 8];
            }
#pragma unroll
            for (int nt = 0; nt < 4; nt++) {
                int n0 = wn + nt * 8;
                bf[nt][0] = Bs[ks + tg][n0 + g];
                bf[nt][1] = Bs[ks + tg + 4][n0 + g];
            }
#pragma unroll
            for (int mt = 0; mt < 4; mt++)
#pragma unroll
                for (int nt = 0; nt < 4; nt++)
                    mma_tf32(acc[mt][nt], af[mt], bf[nt]);
        }

        if (!more) break;
        __syncthreads();
#pragma unroll
        for (int i = 0; i < 4; i++) {
            int f4 = tid + 256 * i;
            int am = f4 >> 3, ak = (f4 & 7) * 4;
            As[ak + 0][am] = f2tf32(pa[i].x);
            As[ak + 1][am] = f2tf32(pa[i].y);
            As[ak + 2][am] = f2tf32(pa[i].z);
            As[ak + 3][am] = f2tf32(pa[i].w);
            int bk = f4 >> 5, bn = (f4 & 31) * 4;
            Bs[bk][bn + 0] = f2tf32(pb[i].x);
            Bs[bk][bn + 1] = f2tf32(pb[i].y);
            Bs[bk][bn + 2] = f2tf32(pb[i].z);
            Bs[bk][bn + 3] = f2tf32(pb[i].w);
        }
        __syncthreads();
        k0 = knext;
    }

    // ---- epilogue: bias + store ----
#pragma unroll
    for (int mt = 0; mt < 4; mt++) {
        int r_lo = by * 128 + wm + mt * 16 + g;
        int r_hi = r_lo + 8;
#pragma unroll
        for (int nt = 0; nt < 4; nt++) {
            int col = bx * 128 + wn + nt * 8 + 2 * tg;
            float b0 = bias[col], b1 = bias[col + 1];
            float2 lo = make_float2(acc[mt][nt][0] + b0, acc[mt][nt][1] + b1);
            float2 hi = make_float2(acc[mt][nt][2] + b0, acc[mt][nt][3] + b1);
            *(float2*)(&C[(size_t)r_lo * N + col]) = lo;
            *(float2*)(&C[(size_t)r_hi * N + col]) = hi;
        }
    }
}

// ---------------------------------------------------------------------------
// Pack q: [B,S,H*128] -> [B,H,S,256] with rope in upper half; fold in SCALE
// ---------------------------------------------------------------------------
__global__ __launch_bounds__(256) void pack_q_kernel(
    const float* __restrict__ qC, float* __restrict__ q)
{
    int gid = blockIdx.x * blockDim.x + threadIdx.x;
    int i = gid & 63;
    int s = (gid >> 6) & (SEQ - 1);
    int h = (gid >> 17) & (NHEADS - 1);
    int b = gid >> 21;

    const float* src = qC + ((size_t)(b * SEQ + s)) * DMODEL + h * HDIM;
    float x1 = src[2 * i], x2 = src[2 * i + 1];

    float inv = powf(10000.0f, -(float)(2 * i) / 128.0f);
    float ang = (float)s * inv;
    float sn, cs; sincosf(ang, &sn, &cs);

    float* dst = q + (((size_t)(b * NHEADS + h)) * SEQ + s) * QKDIM;
    dst[2 * i]       = x1 * SCALE;
    dst[2 * i + 1]   = x2 * SCALE;
    dst[128 + 2 * i] = (x1 * cs - x2 * sn) * SCALE;
    dst[129 + 2 * i] = (x1 * sn + x2 * cs) * SCALE;
}

// ---------------------------------------------------------------------------
// Pack k: raw half from kC, rope half from kr_cache. No scale.
// ---------------------------------------------------------------------------
__global__ __launch_bounds__(256) void pack_k_kernel(
    const float* __restrict__ kC, const float* __restrict__ kr,
    float* __restrict__ k)
{
    int gid = blockIdx.x * blockDim.x + threadIdx.x;
    int i = gid & 63;
    int s = (gid >> 6) & (SEQ - 1);
    int h = (gid >> 17) & (NHEADS - 1);
    int b = gid >> 21;

    size_t soff = ((size_t)(b * SEQ + s)) * DMODEL + h * HDIM;
    const float* raw = kC + soff;
    const float* rot = kr + soff;
    float x1 = rot[2 * i], x2 = rot[2 * i + 1];

    float inv = powf(10000.0f, -(float)(2 * i) / 128.0f);
    float ang = (float)s * inv;
    float sn, cs; sincosf(ang, &sn, &cs);

    float* dst = k + (((size_t)(b * NHEADS + h)) * SEQ + s) * QKDIM;
    dst[2 * i]       = raw[2 * i];
    dst[2 * i + 1]   = raw[2 * i + 1];
    dst[128 + 2 * i] = x1 * cs - x2 * sn;
    dst[129 + 2 * i] = x1 * sn + x2 * cs;
}

// ---------------------------------------------------------------------------
// Flash attention (fp32, causal). BM=BN=64, 256 threads.
// ---------------------------------------------------------------------------
#define QS_LD 260
#define VS_LD 132
#define PS_LD 68
#define FL_SMEM ((64*QS_LD + 64*QS_LD + 64*VS_LD + 64*PS_LD) * 4)

__global__ __launch_bounds__(256) void flash_kernel(
    const float* __restrict__ q,    // [B,H,S,256] scaled
    const float* __restrict__ kk,   // [B,H,S,256]
    const float* __restrict__ vC,   // [B,S,2048]
    float* __restrict__ ctx)        // [B,S,2048]
{
    extern __shared__ float sm[];
    float* qs = sm;                   // 64 x 260
    float* ks = qs + 64 * QS_LD;      // 64 x 260
    float* vs = ks + 64 * QS_LD;      // 64 x 132
    float* ps = vs + 64 * VS_LD;      // 64 x 68

    const int tid = threadIdx.x;
    const int qt  = blockIdx.x;       // q tile 0..31
    const int bh  = blockIdx.y;       // 0..31
    const int b = bh >> 4, h = bh & 15;

    const float* qbase = q + ((size_t)bh * SEQ + qt * 64) * QKDIM;
    for (int i = tid; i < 64 * 64; i += 256) {
        int r = i >> 6, c4 = i & 63;
        *(float4*)(&qs[r * QS_LD + c4 * 4]) =
            *(const float4*)(qbase + (size_t)r * QKDIM + c4 * 4);
    }

    const int rp = tid >> 3;          // 0..31
    const int cg = tid & 7;           // 0..7
    const int r0 = rp * 2, r1 = r0 + 1;
    const int qg0 = qt * 64 + r0, qg1 = qg0 + 1;

    float m0 = -1e30f, m1 = -1e30f, l0 = 0.f, l1 = 0.f;
    float acc0[16], acc1[16];
#pragma unroll
    for (int i = 0; i < 16; i++) { acc0[i] = 0.f; acc1[i] = 0.f; }

    __syncthreads();

    for (int kt = 0; kt <= qt; kt++) {
        const float* kbase = kk + ((size_t)bh * SEQ + kt * 64) * QKDIM;
        for (int i = tid; i < 64 * 64; i += 256) {
            int r = i >> 6, c4 = i & 63;
            *(float4*)(&ks[r * QS_LD + c4 * 4]) =
                *(const float4*)(kbase + (size_t)r * QKDIM + c4 * 4);
        }
        const float* vbase = vC + ((size_t)b * SEQ + kt * 64) * DMODEL + h * HDIM;
        for (int i = tid; i < 64 * 32; i += 256) {
            int r = i >> 5, d4 = i & 31;
            *(float4*)(&vs[r * VS_LD + d4 * 4]) =
                *(const float4*)(vbase + (size_t)r * DMODEL + d4 * 4);
        }
        __syncthreads();

        float s0[8], s1[8];
#pragma unroll
        for (int j = 0; j < 8; j++) { s0[j] = 0.f; s1[j] = 0.f; }
        const float* qr0 = &qs[r0 * QS_LD];
        const float* qr1 = &qs[r1 * QS_LD];
#pragma unroll 4
        for (int d = 0; d < QKDIM; d++) {
            float a0 = qr0[d], a1 = qr1[d];
#pragma unroll
            for (int j = 0; j < 8; j++) {
                float kv = ks[(cg + 8 * j) * QS_LD + d];
                s0[j] += a0 * kv;
                s1[j] += a1 * kv;
            }
        }
        if (kt == qt) {
            int cbase = kt * 64 + cg;
#pragma unroll
            for (int j = 0; j < 8; j++) {
                int c = cbase + 8 * j;
                if (c > qg0) s0[j] = -1e30f;
                if (c > qg1) s1[j] = -1e30f;
            }
        }
        float t0 = s0[0], t1 = s1[0];
#pragma unroll
        for (int j = 1; j < 8; j++) { t0 = fmaxf(t0, s0[j]); t1 = fmaxf(t1, s1[j]); }
        for (int o = 1; o < 8; o <<= 1) {
            t0 = fmaxf(t0, __shfl_xor_sync(0xffffffffu, t0, o));
            t1 = fmaxf(t1, __shfl_xor_sync(0xffffffffu, t1, o));
        }
        float mn0 = fmaxf(m0, t0), mn1 = fmaxf(m1, t1);
        float f0 = __expf(m0 - mn0), f1 = __expf(m1 - mn1);
        m0 = mn0; m1 = mn1;

        float sum0 = 0.f, sum1 = 0.f;
#pragma unroll
        for (int j = 0; j < 8; j++) {
            float p0 = __expf(s0[j] - mn0);
            float p1 = __expf(s1[j] - mn1);
            ps[r0 * PS_LD + cg + 8 * j] = p0;
            ps[r1 * PS_LD + cg + 8 * j] = p1;
            sum0 += p0; sum1 += p1;
        }
        for (int o = 1; o < 8; o <<= 1) {
            sum0 += __shfl_xor_sync(0xffffffffu, sum0, o);
            sum1 += __shfl_xor_sync(0xffffffffu, sum1, o);
        }
        l0 = l0 * f0 + sum0;
        l1 = l1 * f1 + sum1;
#pragma unroll
        for (int i = 0; i < 16; i++) { acc0[i] *= f0; acc1[i] *= f1; }
        __syncthreads();

#pragma unroll 2
        for (int c = 0; c < 64; c++) {
            float p0 = ps[r0 * PS_LD + c];
            float p1 = ps[r1 * PS_LD + c];
            const float* vr = &vs[c * VS_LD + cg];
#pragma unroll
            for (int i = 0; i < 16; i++) {
                float vv = vr[8 * i];
                acc0[i] += p0 * vv;
                acc1[i] += p1 * vv;
            }
        }
        __syncthreads();
    }

    float inv0 = 1.f / l0, inv1 = 1.f / l1;
    float* o0 = ctx + ((size_t)b * SEQ + qg0) * DMODEL + h * HDIM + cg;
    float* o1 = ctx + ((size_t)b * SEQ + qg1) * DMODEL + h * HDIM + cg;
#pragma unroll
    for (int i = 0; i < 16; i++) {
        o0[8 * i] = acc0[i] * inv0;
        o1[8 * i] = acc1[i] * inv1;
    }
}

// ---------------------------------------------------------------------------
// Launch
// ---------------------------------------------------------------------------
extern "C" void kernel_launch(void* const* d_in, const int* in_sizes, int n_in,
                              void* d_out, int out_size)
{
    const float* h     = (const float*)d_in[0];
    const float* W_DKV = (const float*)d_in[1];
    const float* b_DKV = (const float*)d_in[2];
    const float* W_UK  = (const float*)d_in[3];
    const float* b_UK  = (const float*)d_in[4];
    const float* W_UV  = (const float*)d_in[5];
    const float* b_UV  = (const float*)d_in[6];
    const float* W_DQ  = (const float*)d_in[7];
    const float* b_DQ  = (const float*)d_in[8];
    const float* W_UQ  = (const float*)d_in[9];
    const float* b_UQ  = (const float*)d_in[10];
    const float* W_KR  = (const float*)d_in[11];
    const float* b_KR  = (const float*)d_in[12];
    const float* W_O   = (const float*)d_in[13];
    const float* b_O   = (const float*)d_in[14];

    float* out = (float*)d_out;            // [0, OUT_SZ)
    float* cKV = out + OUT_SZ;             // c_KV output
    float* kr  = cKV + CKV_SZ;             // kr_cache output

    float *p_cQ, *p_kC, *p_vC, *p_qC, *p_q, *p_k, *p_ctx;
    cudaGetSymbolAddress((void**)&p_cQ,  g_cQ);
    cudaGetSymbolAddress((void**)&p_kC,  g_kC);
    cudaGetSymbolAddress((void**)&p_vC,  g_vC);
    cudaGetSymbolAddress((void**)&p_qC,  g_qC);
    cudaGetSymbolAddress((void**)&p_q,   g_q);
    cudaGetSymbolAddress((void**)&p_k,   g_k);
    cudaGetSymbolAddress((void**)&p_ctx, g_ctx);

    cudaFuncSetAttribute(flash_kernel,
                         cudaFuncAttributeMaxDynamicSharedMemorySize, FL_SMEM);

    // projections (tf32 tensor cores)
    tf32_gemm_bias<<<dim3(DKV/128,    ROWS/128), 256>>>(ROWS, DKV,    DMODEL, h,    W_DKV, b_DKV, cKV);
    tf32_gemm_bias<<<dim3(DMODEL/128, ROWS/128), 256>>>(ROWS, DMODEL, DMODEL, h,    W_KR,  b_KR,  kr);
    tf32_gemm_bias<<<dim3(DQ/128,     ROWS/128), 256>>>(ROWS, DQ,     DMODEL, h,    W_DQ,  b_DQ,  p_cQ);
    tf32_gemm_bias<<<dim3(DMODEL/128, ROWS/128), 256>>>(ROWS, DMODEL, DKV,    cKV,  W_UK,  b_UK,  p_kC);
    tf32_gemm_bias<<<dim3(DMODEL/128, ROWS/128), 256>>>(ROWS, DMODEL, DKV,    cKV,  W_UV,  b_UV,  p_vC);
    tf32_gemm_bias<<<dim3(DMODEL/128, ROWS/128), 256>>>(ROWS, DMODEL, DQ,     p_cQ, W_UQ,  b_UQ,  p_qC);

    // rope + repack
    int pack_threads = BATCH * NHEADS * SEQ * 64;   // 4194304
    pack_q_kernel<<<pack_threads / 256, 256>>>(p_qC, p_q);
    pack_k_kernel<<<pack_threads / 256, 256>>>(p_kC, kr, p_k);

    // attention
    flash_kernel<<<dim3(SEQ/64, BATCH*NHEADS), 256, FL_SMEM>>>(p_q, p_k, p_vC, p_ctx);

    // output projection
    tf32_gemm_bias<<<dim3(DMODEL/128, ROWS/128), 256>>>(ROWS, DMODEL, DMODEL, p_ctx, W_O, b_O, out);
}

// round 4
// speedup vs baseline: 1.8673x; 1.8673x over previous
#include <cuda_runtime.h>
#include <cuda_bf16.h>
#include <math.h>
#include <stdint.h>

// ---------------------------------------------------------------------------
// Problem constants
// ---------------------------------------------------------------------------
#define BATCH    2
#define SEQ      2048
#define DMODEL   2048
#define DKV      512
#define DQ       1536
#define NHEADS   16
#define HDIM     128
#define ROWS     (BATCH*SEQ)            // 4096
#define QKDIM    256                    // concat(head, rope(head))
#define SCALE    0.0625f                // 1/sqrt(256)

#define OUT_SZ   (BATCH*SEQ*DMODEL)     // 8388608
#define CKV_SZ   (BATCH*SEQ*DKV)        // 2097152

// ---------------------------------------------------------------------------
// Scratch (no cudaMalloc allowed -> __device__ globals)
// ---------------------------------------------------------------------------
__device__ float g_cQ [ROWS*DQ];                 // 4096x1536
__device__ float g_kC [ROWS*DMODEL];             // 4096x2048
__device__ float g_vC [ROWS*DMODEL];             // 4096x2048
__device__ float g_qC [ROWS*DMODEL];             // 4096x2048
__device__ float g_q  [BATCH*NHEADS*SEQ*QKDIM];  // 16M
__device__ float g_k  [BATCH*NHEADS*SEQ*QKDIM];  // 16M
__device__ float g_ctx[ROWS*DMODEL];             // 4096x2048

// ---------------------------------------------------------------------------
// tf32 / cp.async helpers
// ---------------------------------------------------------------------------
__device__ __forceinline__ uint32_t f2tf32(float x) {
    uint32_t r;
    asm("cvt.rna.tf32.f32 %0, %1;" : "=r"(r) : "f"(x));
    return r;
}

__device__ __forceinline__ void mma_tf32(float c[4],
                                         const uint32_t a[4],
                                         const uint32_t b[2]) {
    asm volatile(
        "mma.sync.aligned.m16n8k8.row.col.f32.tf32.tf32.f32 "
        "{%0,%1,%2,%3}, {%4,%5,%6,%7}, {%8,%9}, {%0,%1,%2,%3};\n"
        : "+f"(c[0]), "+f"(c[1]), "+f"(c[2]), "+f"(c[3])
        : "r"(a[0]), "r"(a[1]), "r"(a[2]), "r"(a[3]),
          "r"(b[0]), "r"(b[1]));
}

__device__ __forceinline__ void cp_async16(float* smem_dst, const float* gsrc) {
    uint32_t sa = (uint32_t)__cvta_generic_to_shared(smem_dst);
    asm volatile("cp.async.cg.shared.global [%0], [%1], 16;\n"
                 :: "r"(sa), "l"(gsrc));
}
__device__ __forceinline__ void cp_commit() {
    asm volatile("cp.async.commit_group;\n" ::: "memory");
}
__device__ __forceinline__ void cp_wait2() {
    asm volatile("cp.async.wait_group 2;\n" ::: "memory");
}

// ---------------------------------------------------------------------------
// Pipelined TF32 GEMM: C[M,N] = A[M,K] @ B[K,N] + bias[N]  (row-major fp32)
// BM=BN=128, BK=32, 128 threads (4 warps, 2x2 grid, 64x64 warp tile),
// 3-stage cp.async pipeline. fp32 in smem, cvt->tf32 at fragment load.
// ---------------------------------------------------------------------------
#define GSTAGES 3
#define GBK     32
#define A_LD    36          // (36w: 4g+tg banks all distinct; rows 16B aligned)
#define B_LD    136         // (8tg+g banks all distinct; rows 16B aligned)
#define STAGE_FLOATS (128*A_LD + GBK*B_LD)          // 4608 + 4352 = 8960
#define GEMM_SMEM    (GSTAGES*STAGE_FLOATS*4)       // 107520 bytes

__device__ __forceinline__ void g_load_stage(
    float* As, float* Bs,
    const float* __restrict__ Ab, const float* __restrict__ Bb,
    int k0, int K, int N, int tid)
{
#pragma unroll
    for (int i = 0; i < 8; i++) {
        int c = tid + 128 * i;            // 0..1023
        int am = c >> 3, ak = (c & 7) * 4;
        cp_async16(As + am * A_LD + ak, Ab + (size_t)am * K + k0 + ak);
    }
#pragma unroll
    for (int i = 0; i < 8; i++) {
        int c = tid + 128 * i;
        int bk = c >> 5, bn = (c & 31) * 4;
        cp_async16(Bs + bk * B_LD + bn, Bb + (size_t)(k0 + bk) * N + bn);
    }
}

__global__ __launch_bounds__(128, 2) void tf32_gemm_pipe(
    int M, int N, int K,
    const float* __restrict__ A, const float* __restrict__ B,
    const float* __restrict__ bias, float* __restrict__ C)
{
    extern __shared__ float gsm[];

    const int tid  = threadIdx.x;
    const int bx   = blockIdx.x, by = blockIdx.y;
    const int warp = tid >> 5, lane = tid & 31;
    const int wm   = (warp >> 1) * 64;   // warp M offset
    const int wn   = (warp & 1) * 64;    // warp N offset
    const int g    = lane >> 2;          // 0..7
    const int tg   = lane & 3;           // 0..3

    const float* Ab = A + (size_t)(by * 128) * K;
    const float* Bb = B + bx * 128;

    float acc[4][8][4];
#pragma unroll
    for (int mt = 0; mt < 4; mt++)
#pragma unroll
        for (int nt = 0; nt < 8; nt++)
#pragma unroll
            for (int i = 0; i < 4; i++) acc[mt][nt][i] = 0.f;

    // prologue: fill pipeline
#pragma unroll
    for (int s = 0; s < GSTAGES; s++) {
        if (s * GBK < K)
            g_load_stage(gsm + s * STAGE_FLOATS,
                         gsm + s * STAGE_FLOATS + 128 * A_LD,
                         Ab, Bb, s * GBK, K, N, tid);
        cp_commit();
    }

    int rs = 0;
    for (int k0 = 0; k0 < K; k0 += GBK) {
        cp_wait2();
        __syncthreads();

        float* As = gsm + rs * STAGE_FLOATS;
        float* Bs = As + 128 * A_LD;

#pragma unroll
        for (int ks = 0; ks < GBK; ks += 8) {
            uint32_t af[4][4], bf[8][2];
#pragma unroll
            for (int mt = 0; mt < 4; mt++) {
                const float* ab = As + (wm + mt * 16 + g) * A_LD + ks + tg;
                af[mt][0] = f2tf32(ab[0]);
                af[mt][2] = f2tf32(ab[4]);
                af[mt][1] = f2tf32(ab[8 * A_LD]);
                af[mt][3] = f2tf32(ab[8 * A_LD + 4]);
            }
#pragma unroll
            for (int nt = 0; nt < 8; nt++) {
                int n0 = wn + nt * 8;
                bf[nt][0] = f2tf32(Bs[(ks + tg) * B_LD + n0 + g]);
                bf[nt][1] = f2tf32(Bs[(ks + tg + 4) * B_LD + n0 + g]);
            }
#pragma unroll
            for (int mt = 0; mt < 4; mt++)
#pragma unroll
                for (int nt = 0; nt < 8; nt++)
                    mma_tf32(acc[mt][nt], af[mt], bf[nt]);
        }

        __syncthreads();
        int kl = k0 + GSTAGES * GBK;
        if (kl < K)
            g_load_stage(As, Bs, Ab, Bb, kl, K, N, tid);
        cp_commit();
        rs = rs + 1; if (rs == GSTAGES) rs = 0;
    }

    // epilogue: bias + store
#pragma unroll
    for (int mt = 0; mt < 4; mt++) {
        int r_lo = by * 128 + wm + mt * 16 + g;
        int r_hi = r_lo + 8;
#pragma unroll
        for (int nt = 0; nt < 8; nt++) {
            int col = bx * 128 + wn + nt * 8 + 2 * tg;
            float b0 = bias[col], b1 = bias[col + 1];
            float2 lo = make_float2(acc[mt][nt][0] + b0, acc[mt][nt][1] + b1);
            float2 hi = make_float2(acc[mt][nt][2] + b0, acc[mt][nt][3] + b1);
            *(float2*)(&C[(size_t)r_lo * N + col]) = lo;
            *(float2*)(&C[(size_t)r_hi * N + col]) = hi;
        }
    }
}

// ---------------------------------------------------------------------------
// Pack q: [B,S,H*128] -> [B,H,S,256] with rope in upper half; fold in SCALE
// ---------------------------------------------------------------------------
__global__ __launch_bounds__(256) void pack_q_kernel(
    const float* __restrict__ qC, float* __restrict__ q)
{
    int gid = blockIdx.x * blockDim.x + threadIdx.x;
    int i = gid & 63;
    int s = (gid >> 6) & (SEQ - 1);
    int h = (gid >> 17) & (NHEADS - 1);
    int b = gid >> 21;

    const float* src = qC + ((size_t)(b * SEQ + s)) * DMODEL + h * HDIM;
    float x1 = src[2 * i], x2 = src[2 * i + 1];

    float inv = powf(10000.0f, -(float)(2 * i) / 128.0f);
    float ang = (float)s * inv;
    float sn, cs; sincosf(ang, &sn, &cs);

    float* dst = q + (((size_t)(b * NHEADS + h)) * SEQ + s) * QKDIM;
    dst[2 * i]       = x1 * SCALE;
    dst[2 * i + 1]   = x2 * SCALE;
    dst[128 + 2 * i] = (x1 * cs - x2 * sn) * SCALE;
    dst[129 + 2 * i] = (x1 * sn + x2 * cs) * SCALE;
}

// ---------------------------------------------------------------------------
// Pack k: raw half from kC, rope half from kr_cache. No scale.
// ---------------------------------------------------------------------------
__global__ __launch_bounds__(256) void pack_k_kernel(
    const float* __restrict__ kC, const float* __restrict__ kr,
    float* __restrict__ k)
{
    int gid = blockIdx.x * blockDim.x + threadIdx.x;
    int i = gid & 63;
    int s = (gid >> 6) & (SEQ - 1);
    int h = (gid >> 17) & (NHEADS - 1);
    int b = gid >> 21;

    size_t soff = ((size_t)(b * SEQ + s)) * DMODEL + h * HDIM;
    const float* raw = kC + soff;
    const float* rot = kr + soff;
    float x1 = rot[2 * i], x2 = rot[2 * i + 1];

    float inv = powf(10000.0f, -(float)(2 * i) / 128.0f);
    float ang = (float)s * inv;
    float sn, cs; sincosf(ang, &sn, &cs);

    float* dst = k + (((size_t)(b * NHEADS + h)) * SEQ + s) * QKDIM;
    dst[2 * i]       = raw[2 * i];
    dst[2 * i + 1]   = raw[2 * i + 1];
    dst[128 + 2 * i] = x1 * cs - x2 * sn;
    dst[129 + 2 * i] = x1 * sn + x2 * cs;
}

// ---------------------------------------------------------------------------
// Flash attention (fp32, causal). BM=BN=64, 256 threads. (unchanged)
// ---------------------------------------------------------------------------
#define QS_LD 260
#define VS_LD 132
#define PS_LD 68
#define FL_SMEM ((64*QS_LD + 64*QS_LD + 64*VS_LD + 64*PS_LD) * 4)

__global__ __launch_bounds__(256) void flash_kernel(
    const float* __restrict__ q,    // [B,H,S,256] scaled
    const float* __restrict__ kk,   // [B,H,S,256]
    const float* __restrict__ vC,   // [B,S,2048]
    float* __restrict__ ctx)        // [B,S,2048]
{
    extern __shared__ float sm[];
    float* qs = sm;                   // 64 x 260
    float* ks = qs + 64 * QS_LD;      // 64 x 260
    float* vs = ks + 64 * QS_LD;      // 64 x 132
    float* ps = vs + 64 * VS_LD;      // 64 x 68

    const int tid = threadIdx.x;
    const int qt  = blockIdx.x;       // q tile 0..31
    const int bh  = blockIdx.y;       // 0..31
    const int b = bh >> 4, h = bh & 15;

    const float* qbase = q + ((size_t)bh * SEQ + qt * 64) * QKDIM;
    for (int i = tid; i < 64 * 64; i += 256) {
        int r = i >> 6, c4 = i & 63;
        *(float4*)(&qs[r * QS_LD + c4 * 4]) =
            *(const float4*)(qbase + (size_t)r * QKDIM + c4 * 4);
    }

    const int rp = tid >> 3;          // 0..31
    const int cg = tid & 7;           // 0..7
    const int r0 = rp * 2, r1 = r0 + 1;
    const int qg0 = qt * 64 + r0, qg1 = qg0 + 1;

    float m0 = -1e30f, m1 = -1e30f, l0 = 0.f, l1 = 0.f;
    float acc0[16], acc1[16];
#pragma unroll
    for (int i = 0; i < 16; i++) { acc0[i] = 0.f; acc1[i] = 0.f; }

    __syncthreads();

    for (int kt = 0; kt <= qt; kt++) {
        const float* kbase = kk + ((size_t)bh * SEQ + kt * 64) * QKDIM;
        for (int i = tid; i < 64 * 64; i += 256) {
            int r = i >> 6, c4 = i & 63;
            *(float4*)(&ks[r * QS_LD + c4 * 4]) =
                *(const float4*)(kbase + (size_t)r * QKDIM + c4 * 4);
        }
        const float* vbase = vC + ((size_t)b * SEQ + kt * 64) * DMODEL + h * HDIM;
        for (int i = tid; i < 64 * 32; i += 256) {
            int r = i >> 5, d4 = i & 31;
            *(float4*)(&vs[r * VS_LD + d4 * 4]) =
                *(const float4*)(vbase + (size_t)r * DMODEL + d4 * 4);
        }
        __syncthreads();

        float s0[8], s1[8];
#pragma unroll
        for (int j = 0; j < 8; j++) { s0[j] = 0.f; s1[j] = 0.f; }
        const float* qr0 = &qs[r0 * QS_LD];
        const float* qr1 = &qs[r1 * QS_LD];
#pragma unroll 4
        for (int d = 0; d < QKDIM; d++) {
            float a0 = qr0[d], a1 = qr1[d];
#pragma unroll
            for (int j = 0; j < 8; j++) {
                float kv = ks[(cg + 8 * j) * QS_LD + d];
                s0[j] += a0 * kv;
                s1[j] += a1 * kv;
            }
        }
        if (kt == qt) {
            int cbase = kt * 64 + cg;
#pragma unroll
            for (int j = 0; j < 8; j++) {
                int c = cbase + 8 * j;
                if (c > qg0) s0[j] = -1e30f;
                if (c > qg1) s1[j] = -1e30f;
            }
        }
        float t0 = s0[0], t1 = s1[0];
#pragma unroll
        for (int j = 1; j < 8; j++) { t0 = fmaxf(t0, s0[j]); t1 = fmaxf(t1, s1[j]); }
        for (int o = 1; o < 8; o <<= 1) {
            t0 = fmaxf(t0, __shfl_xor_sync(0xffffffffu, t0, o));
            t1 = fmaxf(t1, __shfl_xor_sync(0xffffffffu, t1, o));
        }
        float mn0 = fmaxf(m0, t0), mn1 = fmaxf(m1, t1);
        float f0 = __expf(m0 - mn0), f1 = __expf(m1 - mn1);
        m0 = mn0; m1 = mn1;

        float sum0 = 0.f, sum1 = 0.f;
#pragma unroll
        for (int j = 0; j < 8; j++) {
            float p0 = __expf(s0[j] - mn0);
            float p1 = __expf(s1[j] - mn1);
            ps[r0 * PS_LD + cg + 8 * j] = p0;
            ps[r1 * PS_LD + cg + 8 * j] = p1;
            sum0 += p0; sum1 += p1;
        }
        for (int o = 1; o < 8; o <<= 1) {
            sum0 += __shfl_xor_sync(0xffffffffu, sum0, o);
            sum1 += __shfl_xor_sync(0xffffffffu, sum1, o);
        }
        l0 = l0 * f0 + sum0;
        l1 = l1 * f1 + sum1;
#pragma unroll
        for (int i = 0; i < 16; i++) { acc0[i] *= f0; acc1[i] *= f1; }
        __syncthreads();

#pragma unroll 2
        for (int c = 0; c < 64; c++) {
            float p0 = ps[r0 * PS_LD + c];
            float p1 = ps[r1 * PS_LD + c];
            const float* vr = &vs[c * VS_LD + cg];
#pragma unroll
            for (int i = 0; i < 16; i++) {
                float vv = vr[8 * i];
                acc0[i] += p0 * vv;
                acc1[i] += p1 * vv;
            }
        }
        __syncthreads();
    }

    float inv0 = 1.f / l0, inv1 = 1.f / l1;
    float* o0 = ctx + ((size_t)b * SEQ + qg0) * DMODEL + h * HDIM + cg;
    float* o1 = ctx + ((size_t)b * SEQ + qg1) * DMODEL + h * HDIM + cg;
#pragma unroll
    for (int i = 0; i < 16; i++) {
        o0[8 * i] = acc0[i] * inv0;
        o1[8 * i] = acc1[i] * inv1;
    }
}

// ---------------------------------------------------------------------------
// Launch
// ---------------------------------------------------------------------------
extern "C" void kernel_launch(void* const* d_in, const int* in_sizes, int n_in,
                              void* d_out, int out_size)
{
    const float* h     = (const float*)d_in[0];
    const float* W_DKV = (const float*)d_in[1];
    const float* b_DKV = (const float*)d_in[2];
    const float* W_UK  = (const float*)d_in[3];
    const float* b_UK  = (const float*)d_in[4];
    const float* W_UV  = (const float*)d_in[5];
    const float* b_UV  = (const float*)d_in[6];
    const float* W_DQ  = (const float*)d_in[7];
    const float* b_DQ  = (const float*)d_in[8];
    const float* W_UQ  = (const float*)d_in[9];
    const float* b_UQ  = (const float*)d_in[10];
    const float* W_KR  = (const float*)d_in[11];
    const float* b_KR  = (const float*)d_in[12];
    const float* W_O   = (const float*)d_in[13];
    const float* b_O   = (const float*)d_in[14];

    float* out = (float*)d_out;            // [0, OUT_SZ)
    float* cKV = out + OUT_SZ;             // c_KV output
    float* kr  = cKV + CKV_SZ;             // kr_cache output

    float *p_cQ, *p_kC, *p_vC, *p_qC, *p_q, *p_k, *p_ctx;
    cudaGetSymbolAddress((void**)&p_cQ,  g_cQ);
    cudaGetSymbolAddress((void**)&p_kC,  g_kC);
    cudaGetSymbolAddress((void**)&p_vC,  g_vC);
    cudaGetSymbolAddress((void**)&p_qC,  g_qC);
    cudaGetSymbolAddress((void**)&p_q,   g_q);
    cudaGetSymbolAddress((void**)&p_k,   g_k);
    cudaGetSymbolAddress((void**)&p_ctx, g_ctx);

    cudaFuncSetAttribute(tf32_gemm_pipe,
                         cudaFuncAttributeMaxDynamicSharedMemorySize, GEMM_SMEM);
    cudaFuncSetAttribute(flash_kernel,
                         cudaFuncAttributeMaxDynamicSharedMemorySize, FL_SMEM);

    // projections (pipelined tf32 tensor cores)
    tf32_gemm_pipe<<<dim3(DKV/128,    ROWS/128), 128, GEMM_SMEM>>>(ROWS, DKV,    DMODEL, h,    W_DKV, b_DKV, cKV);
    tf32_gemm_pipe<<<dim3(DMODEL/128, ROWS/128), 128, GEMM_SMEM>>>(ROWS, DMODEL, DMODEL, h,    W_KR,  b_KR,  kr);
    tf32_gemm_pipe<<<dim3(DQ/128,     ROWS/128), 128, GEMM_SMEM>>>(ROWS, DQ,     DMODEL, h,    W_DQ,  b_DQ,  p_cQ);
    tf32_gemm_pipe<<<dim3(DMODEL/128, ROWS/128), 128, GEMM_SMEM>>>(ROWS, DMODEL, DKV,    cKV,  W_UK,  b_UK,  p_kC);
    tf32_gemm_pipe<<<dim3(DMODEL/128, ROWS/128), 128, GEMM_SMEM>>>(ROWS, DMODEL, DKV,    cKV,  W_UV,  b_UV,  p_vC);
    tf32_gemm_pipe<<<dim3(DMODEL/128, ROWS/128), 128, GEMM_SMEM>>>(ROWS, DMODEL, DQ,     p_cQ, W_UQ,  b_UQ,  p_qC);

    // rope + repack
    int pack_threads = BATCH * NHEADS * SEQ * 64;   // 4194304
    pack_q_kernel<<<pack_threads / 256, 256>>>(p_qC, p_q);
    pack_k_kernel<<<pack_threads / 256, 256>>>(p_kC, kr, p_k);

    // attention
    flash_kernel<<<dim3(SEQ/64, BATCH*NHEADS), 256, FL_SMEM>>>(p_q, p_k, p_vC, p_ctx);

    // output projection
    tf32_gemm_pipe<<<dim3(DMODEL/128, ROWS/128), 128, GEMM_SMEM>>>(ROWS, DMODEL, DMODEL, p_ctx, W_O, b_O, out);
}

// round 5
// speedup vs baseline: 4.0692x; 2.1792x over previous
#include <cuda_runtime.h>
#include <cuda_bf16.h>
#include <math.h>
#include <stdint.h>

// ---------------------------------------------------------------------------
// Problem constants
// ---------------------------------------------------------------------------
#define BATCH    2
#define SEQ      2048
#define DMODEL   2048
#define DKV      512
#define DQ       1536
#define NHEADS   16
#define HDIM     128
#define ROWS     (BATCH*SEQ)            // 4096
#define QKDIM    256
#define SCALE    0.0625f                // 1/sqrt(256)

#define OUT_SZ   (BATCH*SEQ*DMODEL)
#define CKV_SZ   (BATCH*SEQ*DKV)

// ---------------------------------------------------------------------------
// Scratch
// ---------------------------------------------------------------------------
__device__ float g_cQ [ROWS*DQ];
__device__ float g_kC [ROWS*DMODEL];
__device__ float g_vC [ROWS*DMODEL];             // tf32-rounded by UV gemm
__device__ float g_qC [ROWS*DMODEL];
__device__ float g_q  [BATCH*NHEADS*SEQ*QKDIM];  // tf32-rounded, scaled
__device__ float g_k  [BATCH*NHEADS*SEQ*QKDIM];  // tf32-rounded
__device__ float g_ctx[ROWS*DMODEL];

// ---------------------------------------------------------------------------
// tf32 / cp.async helpers
// ---------------------------------------------------------------------------
__device__ __forceinline__ uint32_t f2tf32(float x) {
    uint32_t r;
    asm("cvt.rna.tf32.f32 %0, %1;" : "=r"(r) : "f"(x));
    return r;
}
__device__ __forceinline__ float f2tf32f(float x) {
    return __uint_as_float(f2tf32(x));
}

__device__ __forceinline__ void mma_tf32(float c[4],
                                         const uint32_t a[4],
                                         const uint32_t b[2]) {
    asm volatile(
        "mma.sync.aligned.m16n8k8.row.col.f32.tf32.tf32.f32 "
        "{%0,%1,%2,%3}, {%4,%5,%6,%7}, {%8,%9}, {%0,%1,%2,%3};\n"
        : "+f"(c[0]), "+f"(c[1]), "+f"(c[2]), "+f"(c[3])
        : "r"(a[0]), "r"(a[1]), "r"(a[2]), "r"(a[3]),
          "r"(b[0]), "r"(b[1]));
}

__device__ __forceinline__ void cp_async16(float* smem_dst, const float* gsrc) {
    uint32_t sa = (uint32_t)__cvta_generic_to_shared(smem_dst);
    asm volatile("cp.async.cg.shared.global [%0], [%1], 16;\n"
                 :: "r"(sa), "l"(gsrc));
}
__device__ __forceinline__ void cp_commit() {
    asm volatile("cp.async.commit_group;\n" ::: "memory");
}
__device__ __forceinline__ void cp_wait1() {
    asm volatile("cp.async.wait_group 1;\n" ::: "memory");
}
__device__ __forceinline__ void cp_wait2() {
    asm volatile("cp.async.wait_group 2;\n" ::: "memory");
}

// ---------------------------------------------------------------------------
// Pipelined TF32 GEMM (unchanged from R3 except cvt_out flag)
// ---------------------------------------------------------------------------
#define GSTAGES 3
#define GBK     32
#define A_LD    36
#define B_LD    136
#define STAGE_FLOATS (128*A_LD + GBK*B_LD)
#define GEMM_SMEM    (GSTAGES*STAGE_FLOATS*4)

__device__ __forceinline__ void g_load_stage(
    float* As, float* Bs,
    const float* __restrict__ Ab, const float* __restrict__ Bb,
    int k0, int K, int N, int tid)
{
#pragma unroll
    for (int i = 0; i < 8; i++) {
        int c = tid + 128 * i;
        int am = c >> 3, ak = (c & 7) * 4;
        cp_async16(As + am * A_LD + ak, Ab + (size_t)am * K + k0 + ak);
    }
#pragma unroll
    for (int i = 0; i < 8; i++) {
        int c = tid + 128 * i;
        int bk = c >> 5, bn = (c & 31) * 4;
        cp_async16(Bs + bk * B_LD + bn, Bb + (size_t)(k0 + bk) * N + bn);
    }
}

__global__ __launch_bounds__(128, 2) void tf32_gemm_pipe(
    int M, int N, int K,
    const float* __restrict__ A, const float* __restrict__ B,
    const float* __restrict__ bias, float* __restrict__ C, int cvt_out)
{
    extern __shared__ float gsm[];

    const int tid  = threadIdx.x;
    const int bx   = blockIdx.x, by = blockIdx.y;
    const int warp = tid >> 5, lane = tid & 31;
    const int wm   = (warp >> 1) * 64;
    const int wn   = (warp & 1) * 64;
    const int g    = lane >> 2;
    const int tg   = lane & 3;

    const float* Ab = A + (size_t)(by * 128) * K;
    const float* Bb = B + bx * 128;

    float acc[4][8][4];
#pragma unroll
    for (int mt = 0; mt < 4; mt++)
#pragma unroll
        for (int nt = 0; nt < 8; nt++)
#pragma unroll
            for (int i = 0; i < 4; i++) acc[mt][nt][i] = 0.f;

#pragma unroll
    for (int s = 0; s < GSTAGES; s++) {
        if (s * GBK < K)
            g_load_stage(gsm + s * STAGE_FLOATS,
                         gsm + s * STAGE_FLOATS + 128 * A_LD,
                         Ab, Bb, s * GBK, K, N, tid);
        cp_commit();
    }

    int rs = 0;
    for (int k0 = 0; k0 < K; k0 += GBK) {
        cp_wait2();
        __syncthreads();

        float* As = gsm + rs * STAGE_FLOATS;
        float* Bs = As + 128 * A_LD;

#pragma unroll
        for (int ks = 0; ks < GBK; ks += 8) {
            uint32_t af[4][4], bf[8][2];
#pragma unroll
            for (int mt = 0; mt < 4; mt++) {
                const float* ab = As + (wm + mt * 16 + g) * A_LD + ks + tg;
                af[mt][0] = f2tf32(ab[0]);
                af[mt][2] = f2tf32(ab[4]);
                af[mt][1] = f2tf32(ab[8 * A_LD]);
                af[mt][3] = f2tf32(ab[8 * A_LD + 4]);
            }
#pragma unroll
            for (int nt = 0; nt < 8; nt++) {
                int n0 = wn + nt * 8;
                bf[nt][0] = f2tf32(Bs[(ks + tg) * B_LD + n0 + g]);
                bf[nt][1] = f2tf32(Bs[(ks + tg + 4) * B_LD + n0 + g]);
            }
#pragma unroll
            for (int mt = 0; mt < 4; mt++)
#pragma unroll
                for (int nt = 0; nt < 8; nt++)
                    mma_tf32(acc[mt][nt], af[mt], bf[nt]);
        }

        __syncthreads();
        int kl = k0 + GSTAGES * GBK;
        if (kl < K)
            g_load_stage(As, Bs, Ab, Bb, kl, K, N, tid);
        cp_commit();
        rs = rs + 1; if (rs == GSTAGES) rs = 0;
    }

#pragma unroll
    for (int mt = 0; mt < 4; mt++) {
        int r_lo = by * 128 + wm + mt * 16 + g;
        int r_hi = r_lo + 8;
#pragma unroll
        for (int nt = 0; nt < 8; nt++) {
            int col = bx * 128 + wn + nt * 8 + 2 * tg;
            float b0 = bias[col], b1 = bias[col + 1];
            float2 lo = make_float2(acc[mt][nt][0] + b0, acc[mt][nt][1] + b1);
            float2 hi = make_float2(acc[mt][nt][2] + b0, acc[mt][nt][3] + b1);
            if (cvt_out) {
                lo.x = f2tf32f(lo.x); lo.y = f2tf32f(lo.y);
                hi.x = f2tf32f(hi.x); hi.y = f2tf32f(hi.y);
            }
            *(float2*)(&C[(size_t)r_lo * N + col]) = lo;
            *(float2*)(&C[(size_t)r_hi * N + col]) = hi;
        }
    }
}

// ---------------------------------------------------------------------------
// Pack q (tf32-rounded, scaled)
// ---------------------------------------------------------------------------
__global__ __launch_bounds__(256) void pack_q_kernel(
    const float* __restrict__ qC, float* __restrict__ q)
{
    int gid = blockIdx.x * blockDim.x + threadIdx.x;
    int i = gid & 63;
    int s = (gid >> 6) & (SEQ - 1);
    int h = (gid >> 17) & (NHEADS - 1);
    int b = gid >> 21;

    const float* src = qC + ((size_t)(b * SEQ + s)) * DMODEL + h * HDIM;
    float x1 = src[2 * i], x2 = src[2 * i + 1];

    float inv = powf(10000.0f, -(float)(2 * i) / 128.0f);
    float ang = (float)s * inv;
    float sn, cs; sincosf(ang, &sn, &cs);

    float* dst = q + (((size_t)(b * NHEADS + h)) * SEQ + s) * QKDIM;
    dst[2 * i]       = f2tf32f(x1 * SCALE);
    dst[2 * i + 1]   = f2tf32f(x2 * SCALE);
    dst[128 + 2 * i] = f2tf32f((x1 * cs - x2 * sn) * SCALE);
    dst[129 + 2 * i] = f2tf32f((x1 * sn + x2 * cs) * SCALE);
}

// ---------------------------------------------------------------------------
// Pack k (tf32-rounded)
// ---------------------------------------------------------------------------
__global__ __launch_bounds__(256) void pack_k_kernel(
    const float* __restrict__ kC, const float* __restrict__ kr,
    float* __restrict__ k)
{
    int gid = blockIdx.x * blockDim.x + threadIdx.x;
    int i = gid & 63;
    int s = (gid >> 6) & (SEQ - 1);
    int h = (gid >> 17) & (NHEADS - 1);
    int b = gid >> 21;

    size_t soff = ((size_t)(b * SEQ + s)) * DMODEL + h * HDIM;
    const float* raw = kC + soff;
    const float* rot = kr + soff;
    float x1 = rot[2 * i], x2 = rot[2 * i + 1];

    float inv = powf(10000.0f, -(float)(2 * i) / 128.0f);
    float ang = (float)s * inv;
    float sn, cs; sincosf(ang, &sn, &cs);

    float* dst = k + (((size_t)(b * NHEADS + h)) * SEQ + s) * QKDIM;
    dst[2 * i]       = f2tf32f(raw[2 * i]);
    dst[2 * i + 1]   = f2tf32f(raw[2 * i + 1]);
    dst[128 + 2 * i] = f2tf32f(x1 * cs - x2 * sn);
    dst[129 + 2 * i] = f2tf32f(x1 * sn + x2 * cs);
}

// ---------------------------------------------------------------------------
// TF32 tensor-core flash attention. BM=BN=64, 128 threads (4 warps over M).
// All smem operands pre-rounded to tf32 — no cvt in inner loop.
// cp.async choreography: k(kt+1) overlaps P@V; v(kt) overlaps S-compute.
// ---------------------------------------------------------------------------
#define QS_LD 260
#define KS_LD 260
#define VS_LD 136
#define PS_LD 68
#define FL_SMEM ((64*QS_LD + 64*KS_LD + 64*VS_LD + 64*PS_LD) * 4)

__global__ __launch_bounds__(128, 1) void flash_tf32(
    const float* __restrict__ q,    // [B,H,S,256] tf32, scaled
    const float* __restrict__ kk,   // [B,H,S,256] tf32
    const float* __restrict__ vC,   // [B,S,2048]  tf32
    float* __restrict__ ctx)        // [B,S,2048]
{
    extern __shared__ float sm[];
    float* qs = sm;
    float* ks = qs + 64 * QS_LD;
    float* vs = ks + 64 * KS_LD;
    float* ps = vs + 64 * VS_LD;

    const int tid  = threadIdx.x;
    const int warp = tid >> 5, lane = tid & 31;
    const int g    = lane >> 2;     // 0..7
    const int tg   = lane & 3;      // 0..3
    const int wm   = warp * 16;     // warp row offset in tile

    const int qt = blockIdx.x;      // 0..31
    const int bh = blockIdx.y;      // 0..31
    const int b = bh >> 4, h = bh & 15;

    // ---- issue q + k(0) as group 0, v(0) as group 1 ----
    const float* qbase = q + ((size_t)bh * SEQ + qt * 64) * QKDIM;
#pragma unroll
    for (int i = 0; i < 32; i++) {
        int c = tid + 128 * i;
        int r = c >> 6, c4 = (c & 63) * 4;
        cp_async16(qs + r * QS_LD + c4, qbase + (size_t)r * QKDIM + c4);
    }
    const float* kb0 = kk + ((size_t)bh * SEQ) * QKDIM;
#pragma unroll
    for (int i = 0; i < 32; i++) {
        int c = tid + 128 * i;
        int r = c >> 6, c4 = (c & 63) * 4;
        cp_async16(ks + r * KS_LD + c4, kb0 + (size_t)r * QKDIM + c4);
    }
    cp_commit();
    const float* vb0 = vC + ((size_t)b * SEQ) * DMODEL + h * HDIM;
#pragma unroll
    for (int i = 0; i < 16; i++) {
        int c = tid + 128 * i;
        int r = c >> 5, d4 = (c & 31) * 4;
        cp_async16(vs + r * VS_LD + d4, vb0 + (size_t)r * DMODEL + d4);
    }
    cp_commit();

    float m0 = -1e30f, m1 = -1e30f, l0 = 0.f, l1 = 0.f;
    float oacc[16][4];
#pragma unroll
    for (int nt = 0; nt < 16; nt++)
#pragma unroll
        for (int i = 0; i < 4; i++) oacc[nt][i] = 0.f;

    const int rg0 = qt * 64 + wm + g;   // global row of c0/c1
    const int rg1 = rg0 + 8;            // global row of c2/c3

    for (int kt = 0; kt <= qt; kt++) {
        cp_wait1();            // k(kt) (and q) arrived
        __syncthreads();

        // ---- S = Q . K^T  (warp rows wm..wm+15, all 64 cols) ----
        float sacc[8][4];
#pragma unroll
        for (int nt = 0; nt < 8; nt++)
#pragma unroll
            for (int i = 0; i < 4; i++) sacc[nt][i] = 0.f;

#pragma unroll 4
        for (int kd = 0; kd < QKDIM; kd += 8) {
            uint32_t af[4], bf[8][2];
            const float* qa = qs + (wm + g) * QS_LD + kd + tg;
            af[0] = __float_as_uint(qa[0]);
            af[2] = __float_as_uint(qa[4]);
            af[1] = __float_as_uint(qa[8 * QS_LD]);
            af[3] = __float_as_uint(qa[8 * QS_LD + 4]);
#pragma unroll
            for (int nt = 0; nt < 8; nt++) {
                const float* kbp = ks + (8 * nt + g) * KS_LD + kd + tg;
                bf[nt][0] = __float_as_uint(kbp[0]);
                bf[nt][1] = __float_as_uint(kbp[4]);
            }
#pragma unroll
            for (int nt = 0; nt < 8; nt++)
                mma_tf32(sacc[nt], af, bf[nt]);
        }

        // ---- causal mask (diagonal tile only) ----
        if (kt == qt) {
            int cb = kt * 64 + 2 * tg;
#pragma unroll
            for (int nt = 0; nt < 8; nt++) {
                int c0 = cb + 8 * nt, c1 = c0 + 1;
                if (c0 > rg0) sacc[nt][0] = -1e30f;
                if (c1 > rg0) sacc[nt][1] = -1e30f;
                if (c0 > rg1) sacc[nt][2] = -1e30f;
                if (c1 > rg1) sacc[nt][3] = -1e30f;
            }
        }

        // ---- online softmax (rows g and g+8; quad shuffle over tg) ----
        float tA = -1e30f, tB = -1e30f;
#pragma unroll
        for (int nt = 0; nt < 8; nt++) {
            tA = fmaxf(tA, fmaxf(sacc[nt][0], sacc[nt][1]));
            tB = fmaxf(tB, fmaxf(sacc[nt][2], sacc[nt][3]));
        }
        tA = fmaxf(tA, __shfl_xor_sync(0xffffffffu, tA, 1));
        tA = fmaxf(tA, __shfl_xor_sync(0xffffffffu, tA, 2));
        tB = fmaxf(tB, __shfl_xor_sync(0xffffffffu, tB, 1));
        tB = fmaxf(tB, __shfl_xor_sync(0xffffffffu, tB, 2));

        float mn0 = fmaxf(m0, tA), mn1 = fmaxf(m1, tB);
        float f0 = __expf(m0 - mn0), f1 = __expf(m1 - mn1);
        m0 = mn0; m1 = mn1;

        float sum0 = 0.f, sum1 = 0.f;
        float* pr0 = ps + (wm + g) * PS_LD + 2 * tg;
        float* pr1 = ps + (wm + g + 8) * PS_LD + 2 * tg;
#pragma unroll
        for (int nt = 0; nt < 8; nt++) {
            float p0 = __expf(sacc[nt][0] - mn0);
            float p1 = __expf(sacc[nt][1] - mn0);
            float p2 = __expf(sacc[nt][2] - mn1);
            float p3 = __expf(sacc[nt][3] - mn1);
            sum0 += p0 + p1;
            sum1 += p2 + p3;
            *(float2*)(pr0 + 8 * nt) = make_float2(f2tf32f(p0), f2tf32f(p1));
            *(float2*)(pr1 + 8 * nt) = make_float2(f2tf32f(p2), f2tf32f(p3));
        }
        sum0 += __shfl_xor_sync(0xffffffffu, sum0, 1);
        sum0 += __shfl_xor_sync(0xffffffffu, sum0, 2);
        sum1 += __shfl_xor_sync(0xffffffffu, sum1, 1);
        sum1 += __shfl_xor_sync(0xffffffffu, sum1, 2);
        l0 = l0 * f0 + sum0;
        l1 = l1 * f1 + sum1;

        __syncthreads();       // all warps done reading ks, ps visible

        // ---- prefetch k(kt+1) (overlaps P@V) ----
        if (kt < qt) {
            const float* kb = kk + ((size_t)bh * SEQ + (kt + 1) * 64) * QKDIM;
#pragma unroll
            for (int i = 0; i < 32; i++) {
                int c = tid + 128 * i;
                int r = c >> 6, c4 = (c & 63) * 4;
                cp_async16(ks + r * KS_LD + c4, kb + (size_t)r * QKDIM + c4);
            }
        }
        cp_commit();

        cp_wait1();            // v(kt) arrived (k(kt+1) may be in flight)
        __syncthreads();

        // ---- rescale O, then O += P @ V ----
#pragma unroll
        for (int nt = 0; nt < 16; nt++) {
            oacc[nt][0] *= f0; oacc[nt][1] *= f0;
            oacc[nt][2] *= f1; oacc[nt][3] *= f1;
        }
#pragma unroll
        for (int kd = 0; kd < 64; kd += 8) {
            uint32_t af[4];
            const float* pa = ps + (wm + g) * PS_LD + kd + tg;
            af[0] = __float_as_uint(pa[0]);
            af[2] = __float_as_uint(pa[4]);
            af[1] = __float_as_uint(pa[8 * PS_LD]);
            af[3] = __float_as_uint(pa[8 * PS_LD + 4]);
#pragma unroll
            for (int nt = 0; nt < 16; nt++) {
                uint32_t bf[2];
                const float* vb = vs + (kd + tg) * VS_LD + 8 * nt + g;
                bf[0] = __float_as_uint(vb[0]);
                bf[1] = __float_as_uint(vb[4 * VS_LD]);
                mma_tf32(oacc[nt], af, bf);
            }
        }

        __syncthreads();       // vs/ps consumed

        // ---- prefetch v(kt+1) (overlaps next S) ----
        if (kt < qt) {
            const float* vb = vC + ((size_t)b * SEQ + (kt + 1) * 64) * DMODEL + h * HDIM;
#pragma unroll
            for (int i = 0; i < 16; i++) {
                int c = tid + 128 * i;
                int r = c >> 5, d4 = (c & 31) * 4;
                cp_async16(vs + r * VS_LD + d4, vb + (size_t)r * DMODEL + d4);
            }
        }
        cp_commit();
    }

    // ---- epilogue ----
    float inv0 = 1.f / l0, inv1 = 1.f / l1;
    float* o0 = ctx + ((size_t)b * SEQ + rg0) * DMODEL + h * HDIM + 2 * tg;
    float* o1 = ctx + ((size_t)b * SEQ + rg1) * DMODEL + h * HDIM + 2 * tg;
#pragma unroll
    for (int nt = 0; nt < 16; nt++) {
        *(float2*)(o0 + 8 * nt) = make_float2(oacc[nt][0] * inv0, oacc[nt][1] * inv0);
        *(float2*)(o1 + 8 * nt) = make_float2(oacc[nt][2] * inv1, oacc[nt][3] * inv1);
    }
}

// ---------------------------------------------------------------------------
// Launch
// ---------------------------------------------------------------------------
extern "C" void kernel_launch(void* const* d_in, const int* in_sizes, int n_in,
                              void* d_out, int out_size)
{
    const float* h     = (const float*)d_in[0];
    const float* W_DKV = (const float*)d_in[1];
    const float* b_DKV = (const float*)d_in[2];
    const float* W_UK  = (const float*)d_in[3];
    const float* b_UK  = (const float*)d_in[4];
    const float* W_UV  = (const float*)d_in[5];
    const float* b_UV  = (const float*)d_in[6];
    const float* W_DQ  = (const float*)d_in[7];
    const float* b_DQ  = (const float*)d_in[8];
    const float* W_UQ  = (const float*)d_in[9];
    const float* b_UQ  = (const float*)d_in[10];
    const float* W_KR  = (const float*)d_in[11];
    const float* b_KR  = (const float*)d_in[12];
    const float* W_O   = (const float*)d_in[13];
    const float* b_O   = (const float*)d_in[14];

    float* out = (float*)d_out;
    float* cKV = out + OUT_SZ;
    float* kr  = cKV + CKV_SZ;

    float *p_cQ, *p_kC, *p_vC, *p_qC, *p_q, *p_k, *p_ctx;
    cudaGetSymbolAddress((void**)&p_cQ,  g_cQ);
    cudaGetSymbolAddress((void**)&p_kC,  g_kC);
    cudaGetSymbolAddress((void**)&p_vC,  g_vC);
    cudaGetSymbolAddress((void**)&p_qC,  g_qC);
    cudaGetSymbolAddress((void**)&p_q,   g_q);
    cudaGetSymbolAddress((void**)&p_k,   g_k);
    cudaGetSymbolAddress((void**)&p_ctx, g_ctx);

    cudaFuncSetAttribute(tf32_gemm_pipe,
                         cudaFuncAttributeMaxDynamicSharedMemorySize, GEMM_SMEM);
    cudaFuncSetAttribute(flash_tf32,
                         cudaFuncAttributeMaxDynamicSharedMemorySize, FL_SMEM);

    // projections
    tf32_gemm_pipe<<<dim3(DKV/128,    ROWS/128), 128, GEMM_SMEM>>>(ROWS, DKV,    DMODEL, h,    W_DKV, b_DKV, cKV, 0);
    tf32_gemm_pipe<<<dim3(DMODEL/128, ROWS/128), 128, GEMM_SMEM>>>(ROWS, DMODEL, DMODEL, h,    W_KR,  b_KR,  kr, 0);
    tf32_gemm_pipe<<<dim3(DQ/128,     ROWS/128), 128, GEMM_SMEM>>>(ROWS, DQ,     DMODEL, h,    W_DQ,  b_DQ,  p_cQ, 0);
    tf32_gemm_pipe<<<dim3(DMODEL/128, ROWS/128), 128, GEMM_SMEM>>>(ROWS, DMODEL, DKV,    cKV,  W_UK,  b_UK,  p_kC, 0);
    tf32_gemm_pipe<<<dim3(DMODEL/128, ROWS/128), 128, GEMM_SMEM>>>(ROWS, DMODEL, DKV,    cKV,  W_UV,  b_UV,  p_vC, 1);
    tf32_gemm_pipe<<<dim3(DMODEL/128, ROWS/128), 128, GEMM_SMEM>>>(ROWS, DMODEL, DQ,     p_cQ, W_UQ,  b_UQ,  p_qC, 0);

    // rope + repack (tf32 outputs)
    int pack_threads = BATCH * NHEADS * SEQ * 64;
    pack_q_kernel<<<pack_threads / 256, 256>>>(p_qC, p_q);
    pack_k_kernel<<<pack_threads / 256, 256>>>(p_kC, kr, p_k);

    // attention (tf32 tensor cores)
    flash_tf32<<<dim3(SEQ/64, BATCH*NHEADS), 128, FL_SMEM>>>(p_q, p_k, p_vC, p_ctx);

    // output projection
    tf32_gemm_pipe<<<dim3(DMODEL/128, ROWS/128), 128, GEMM_SMEM>>>(ROWS, DMODEL, DMODEL, p_ctx, W_O, b_O, out, 0);
}